// round 16
// baseline (speedup 1.0000x reference)
#include <cuda_runtime.h>
#include <cuda_bf16.h>
#include <math.h>
#include <stdint.h>

#define BSZ   512
#define SLEN  63
#define DD    256
#define VDIM  512
#define RR    196
#define NOUTD 3000
#define STK   (SLEN + 2)

// ---------------- scratch (static device arrays; no allocation) -------------
__device__ float g_vv   [(size_t)BSZ * RR * DD];
__device__ float g_wvi  [(size_t)BSZ * RR * DD];
__device__ float g_gl   [(size_t)BSZ * SLEN * 768];
__device__ float g_buffh[(size_t)BSZ * SLEN * DD];
__device__ float g_buffc[(size_t)BSZ * SLEN * DD];
__device__ float g_stackh[(size_t)BSZ * STK * DD];
__device__ float g_stackc[(size_t)BSZ * STK * DD];
__device__ float g_gates[(size_t)BSZ * 1280];
__device__ float g_r    [BSZ * DD];
__device__ float g_wq   [BSZ * DD];
__device__ float g_att  [BSZ * DD];
__device__ float g_hid  [BSZ * DD];
__device__ float g_biuo [768];
__device__ unsigned g_bc[8];
__device__ unsigned g_bg[8];
__device__ unsigned g_v2done[784];
__device__ unsigned g_vvdone[784];
__device__ unsigned g_q2done[252];
__device__ unsigned g_leafdone[252];
__device__ unsigned g_combcnt;

// bf16 split buffers
__device__ __nv_bfloat16 g_v2   [(size_t)BSZ * RR * (2 * VDIM)];
__device__ __nv_bfloat16 g_vv2  [(size_t)BSZ * RR * (2 * DD)];
__device__ __nv_bfloat16 g_q2   [(size_t)BSZ * SLEN * (2 * DD)];
__device__ __nv_bfloat16 g_w3vv [256 * 3 * VDIM];
__device__ __nv_bfloat16 g_w3wv [256 * 3 * DD];
__device__ __nv_bfloat16 g_w3iuo[768 * 3 * DD];

// ---------------- packed f32x2 helpers ---------------------------------------
__device__ __forceinline__ unsigned long long pk2(float lo, float hi) {
    unsigned long long r;
    asm("mov.b64 %0, {%1, %2};" : "=l"(r) : "f"(lo), "f"(hi));
    return r;
}
__device__ __forceinline__ void upk2(unsigned long long v, float& lo, float& hi) {
    asm("mov.b64 {%0, %1}, %2;" : "=f"(lo), "=f"(hi) : "l"(v));
}
__device__ __forceinline__ unsigned long long ff2(unsigned long long a,
                                                  unsigned long long b,
                                                  unsigned long long c) {
    unsigned long long d;
    asm("fma.rn.f32x2 %0, %1, %2, %3;" : "=l"(d) : "l"(a), "l"(b), "l"(c));
    return d;
}
__device__ __forceinline__ float sigm(float x) { return 1.0f / (1.0f + expf(-x)); }

__device__ __forceinline__ uint32_t smem_u32(const void* p) {
    uint32_t a;
    asm("{ .reg .u64 t; cvta.to.shared.u64 t, %1; cvt.u32.u64 %0, t; }"
        : "=r"(a) : "l"(p));
    return a;
}
__device__ __forceinline__ void ldmx4(uint32_t& r0, uint32_t& r1,
                                      uint32_t& r2, uint32_t& r3, uint32_t addr) {
    asm volatile("ldmatrix.sync.aligned.m8n8.x4.shared.b16 {%0,%1,%2,%3}, [%4];"
                 : "=r"(r0), "=r"(r1), "=r"(r2), "=r"(r3) : "r"(addr));
}
__device__ __forceinline__ void mma16816(float& d0, float& d1, float& d2, float& d3,
                                         uint32_t a0, uint32_t a1, uint32_t a2, uint32_t a3,
                                         uint32_t b0, uint32_t b1) {
    asm volatile("mma.sync.aligned.m16n8k16.row.col.f32.bf16.bf16.f32 "
                 "{%0,%1,%2,%3}, {%4,%5,%6,%7}, {%8,%9}, {%0,%1,%2,%3};"
                 : "+f"(d0), "+f"(d1), "+f"(d2), "+f"(d3)
                 : "r"(a0), "r"(a1), "r"(a2), "r"(a3), "r"(b0), "r"(b1));
}

__device__ __forceinline__ float apply_act(int act, int col, float x) {
    int e = act;
    if (act == 3) e = ((col >> 8) == 1) ? 1 : 2;
    if (e == 1)      return tanhf(x);
    else if (e == 2) return sigm(x);
    return x;
}

// ---------------- shared-memory layouts ---------------------------------------
#define APAD 72
struct MmaSmem {
    __nv_bfloat16 As[128 * APAD];
    __nv_bfloat16 Bs[64 * APAD];
};
struct ScanSmem {
    float As[16][68];
    float Ws[16][68];
    int   sh_op[64];
    int   sh_p[64];
    int   sh_any;
};

// ---------------------------------------------------------------------------
// Tensor-core (HMMA) split-bf16 GEMM core, tile 128(M) x 64(N). Proven form.
// ---------------------------------------------------------------------------
__device__ void mma_core(MmaSmem* sm,
                         const __nv_bfloat16* __restrict__ A2,
                         const __nv_bfloat16* __restrict__ W3,
                         const float* __restrict__ bias,
                         float* __restrict__ Cf,
                         __nv_bfloat16* __restrict__ Chl,
                         int K, int ldc, int coloff, int act,
                         long bm, int bn)
{
    __nv_bfloat16* As = sm->As;
    __nv_bfloat16* Bs = sm->Bs;

    const int tid = threadIdx.x;
    const int wid = tid >> 5, lane = tid & 31;
    const int warp_m = wid & 3, warp_n = wid >> 2;

    const int nc = K / 64;
    const int vchunks = 3 * nc;
    const long lda = 2L * K;
    const long ldw = 3L * K;

    const int a_row = (lane & 7) + ((lane & 8) ? 8 : 0);
    const int a_col = (lane & 16) ? 8 : 0;
    const int b_row = (lane & 7) + ((lane & 16) ? 8 : 0);
    const int b_col = (lane & 8) ? 8 : 0;
    const uint32_t as_base = smem_u32(As);
    const uint32_t bs_base = smem_u32(Bs);

    float d[2][4][4];
#pragma unroll
    for (int mt = 0; mt < 2; mt++)
#pragma unroll
        for (int nt = 0; nt < 4; nt++)
#pragma unroll
            for (int e = 0; e < 4; e++) d[mt][nt][e] = 0.0f;

    uint4 pa[4], pb[2];
    {
#pragma unroll
        for (int q = 0; q < 4; q++) {
            const int u = tid + 256 * q;
            pa[q] = *(const uint4*)(A2 + (bm + (u >> 3)) * lda + (u & 7) * 8);
        }
#pragma unroll
        for (int q = 0; q < 2; q++) {
            const int u = tid + 256 * q;
            pb[q] = *(const uint4*)(W3 + (long)(bn + (u >> 3)) * ldw + (u & 7) * 8);
        }
    }

    for (int c = 0; c < vchunks; c++) {
#pragma unroll
        for (int q = 0; q < 4; q++) {
            const int u = tid + 256 * q;
            *(uint4*)(As + (u >> 3) * APAD + (u & 7) * 8) = pa[q];
        }
#pragma unroll
        for (int q = 0; q < 2; q++) {
            const int u = tid + 256 * q;
            *(uint4*)(Bs + (u >> 3) * APAD + (u & 7) * 8) = pb[q];
        }
        __syncthreads();

        if (c + 1 < vchunks) {
            const int cn = c + 1;
            const long ca = (long)((cn < 2 * nc) ? cn : (cn - 2 * nc)) * 64;
            const long cw = (long)cn * 64;
#pragma unroll
            for (int q = 0; q < 4; q++) {
                const int u = tid + 256 * q;
                pa[q] = *(const uint4*)(A2 + (bm + (u >> 3)) * lda + ca + (u & 7) * 8);
            }
#pragma unroll
            for (int q = 0; q < 2; q++) {
                const int u = tid + 256 * q;
                pb[q] = *(const uint4*)(W3 + (long)(bn + (u >> 3)) * ldw + cw + (u & 7) * 8);
            }
        }

#pragma unroll
        for (int kk = 0; kk < 4; kk++) {
            uint32_t b0, b1, b2, b3, b4, b5, b6, b7;
            {
                const int r = warp_n * 32 + b_row;
                const int cc = kk * 16 + b_col;
                ldmx4(b0, b1, b2, b3, bs_base + (r * APAD + cc) * 2);
                ldmx4(b4, b5, b6, b7, bs_base + ((r + 16) * APAD + cc) * 2);
            }
#pragma unroll
            for (int mt = 0; mt < 2; mt++) {
                uint32_t a0, a1, a2, a3;
                const int r = warp_m * 32 + mt * 16 + a_row;
                const int cc = kk * 16 + a_col;
                ldmx4(a0, a1, a2, a3, as_base + (r * APAD + cc) * 2);
                mma16816(d[mt][0][0], d[mt][0][1], d[mt][0][2], d[mt][0][3],
                         a0, a1, a2, a3, b0, b1);
                mma16816(d[mt][1][0], d[mt][1][1], d[mt][1][2], d[mt][1][3],
                         a0, a1, a2, a3, b2, b3);
                mma16816(d[mt][2][0], d[mt][2][1], d[mt][2][2], d[mt][2][3],
                         a0, a1, a2, a3, b4, b5);
                mma16816(d[mt][3][0], d[mt][3][1], d[mt][3][2], d[mt][3][3],
                         a0, a1, a2, a3, b6, b7);
            }
        }
        __syncthreads();
    }

    const int qrow = lane >> 2;
    const int qcol = (lane & 3) * 2;
#pragma unroll
    for (int mt = 0; mt < 2; mt++) {
#pragma unroll
        for (int nt = 0; nt < 4; nt++) {
            const int colg = bn + warp_n * 32 + nt * 8 + qcol;
            const float bv0 = bias ? bias[colg]     : 0.0f;
            const float bv1 = bias ? bias[colg + 1] : 0.0f;
#pragma unroll
            for (int h = 0; h < 2; h++) {
                const long grow = bm + warp_m * 32 + mt * 16 + qrow + h * 8;
                float x0 = apply_act(act, coloff + colg,     d[mt][nt][2*h+0] + bv0);
                float x1 = apply_act(act, coloff + colg + 1, d[mt][nt][2*h+1] + bv1);
                *(float2*)(Cf + grow * ldc + coloff + colg) = make_float2(x0, x1);
                if (Chl) {
                    const __nv_bfloat16 h0 = __float2bfloat16(x0);
                    const __nv_bfloat16 h1 = __float2bfloat16(x1);
                    *(__nv_bfloat162*)(Chl + grow * 512 + colg) = __nv_bfloat162(h0, h1);
                    *(__nv_bfloat162*)(Chl + grow * 512 + 256 + colg) = __nv_bfloat162(
                        __float2bfloat16(x0 - __bfloat162float(h0)),
                        __float2bfloat16(x1 - __bfloat162float(h1)));
                }
            }
        }
    }
}

// ---------------------------------------------------------------------------
// Persistent shift-reduce scan core (proven), 8 btiles x 20 ctiles.
// ---------------------------------------------------------------------------
__device__ __forceinline__ void btile_bar(int bt, unsigned& mygen)
{
    __threadfence();
    __syncthreads();
    if (threadIdx.x == 0) {
        if (atomicAdd(&g_bc[bt], 1u) == 19u) {
            atomicExch(&g_bc[bt], 0u);
            __threadfence();
            atomicAdd(&g_bg[bt], 1u);
        } else {
            while (atomicAdd(&g_bg[bt], 0u) <= mygen) { }
        }
        mygen++;
    }
    __syncthreads();
}

__device__ void scan_core(ScanSmem* sm, int scanblk,
                          const int* __restrict__ ops,
                          const float* __restrict__ Ui, const float* __restrict__ Uo,
                          const float* __restrict__ Uu, const float* __restrict__ Uf,
                          const float* __restrict__ Uib, const float* __restrict__ Uob,
                          const float* __restrict__ Uub, const float* __restrict__ Ufb)
{
    const int tid = threadIdx.x;
    const int bt = scanblk / 20;
    const int ct = scanblk % 20;
    const int b0 = bt * 64;
    const int seg = ct >> 2;
    const int colbase = (ct & 3) * 64;
    const float* W = (seg == 0) ? Ui : (seg == 1) ? Uo : (seg == 2) ? Uu : Uf;

    const int tx = tid & 15, ty = tid >> 4;
    const int lr = tid >> 2, lc = tid & 3;

    unsigned mygen = 0;
    if (tid == 0) mygen = atomicAdd(&g_bg[bt], 0u);
    if (tid < 64) sm->sh_p[tid] = 0;
    __syncthreads();

    for (int t = 0; t < SLEN; t++) {
        if (tid == 0) sm->sh_any = 0;
        __syncthreads();
        if (tid < 64) {
            const int o = ops[(b0 + tid) * SLEN + t];
            sm->sh_op[tid] = o;
            if (o == 1) sm->sh_any = 1;
        }
        __syncthreads();

        if (sm->sh_any) {
            const int pcur = sm->sh_p[lr];
            const float* Wp = W + (long)(colbase + lr) * DD;
            const float* SHb = g_stackh + (long)(b0 + lr) * STK * DD;
            const float* Sr = SHb + (long)max(pcur - 1, 0) * DD;
            const float* Sl = SHb + (long)max(pcur - 2, 0) * DD;

            unsigned long long acc[2][4];
#pragma unroll
            for (int p = 0; p < 2; p++)
#pragma unroll
                for (int c = 0; c < 4; c++) acc[p][c] = 0ULL;

            for (int k0 = 0; k0 < DD; k0 += 16) {
                float4 av;
                if (seg < 3) {
                    const float4 x = *(const float4*)(Sr + k0 + lc*4);
                    const float4 y = *(const float4*)(Sl + k0 + lc*4);
                    av = make_float4(x.x+y.x, x.y+y.y, x.z+y.z, x.w+y.w);
                } else if (seg == 3) {
                    av = *(const float4*)(Sl + k0 + lc*4);
                } else {
                    av = *(const float4*)(Sr + k0 + lc*4);
                }
                const float4 wv = *(const float4*)(Wp + k0 + lc*4);
                __syncthreads();
                sm->As[lc*4+0][lr] = av.x; sm->As[lc*4+1][lr] = av.y;
                sm->As[lc*4+2][lr] = av.z; sm->As[lc*4+3][lr] = av.w;
                sm->Ws[lc*4+0][lr] = wv.x; sm->Ws[lc*4+1][lr] = wv.y;
                sm->Ws[lc*4+2][lr] = wv.z; sm->Ws[lc*4+3][lr] = wv.w;
                __syncthreads();
#pragma unroll
                for (int k = 0; k < 16; k++) {
                    const float4 aa = *(const float4*)&sm->As[k][ty*4];
                    const float4 bb = *(const float4*)&sm->Ws[k][tx*4];
                    unsigned long long ap[2] = { pk2(aa.x,aa.y), pk2(aa.z,aa.w) };
                    unsigned long long bd[4] = { pk2(bb.x,bb.x), pk2(bb.y,bb.y),
                                                 pk2(bb.z,bb.z), pk2(bb.w,bb.w) };
#pragma unroll
                    for (int p = 0; p < 2; p++)
#pragma unroll
                        for (int c = 0; c < 4; c++)
                            acc[p][c] = ff2(ap[p], bd[c], acc[p][c]);
                }
            }
#pragma unroll
            for (int p = 0; p < 2; p++) {
                const long row = b0 + ty*4 + p*2;
#pragma unroll
                for (int c = 0; c < 4; c++) {
                    const int col = seg * 256 + colbase + tx*4 + c;
                    float lo, hi; upk2(acc[p][c], lo, hi);
                    g_gates[row * 1280 + col] = lo;
                    g_gates[(row+1) * 1280 + col] = hi;
                }
            }
            btile_bar(bt, mygen);
        }

        if (ct < 16) {
            const int bl = tid >> 2;
            const int d = ct * 16 + (tid & 3) * 4;
            const int op = sm->sh_op[bl];
            const int p = sm->sh_p[bl];
            const int b = b0 + bl;
            const long base = (long)b * STK * DD;
            if (op == 1) {
                const int rix = max(p - 1, 0);
                const int lix = max(p - 2, 0);
                const float* G = g_gates + (long)b * 1280;
                const float4 gi4 = *(const float4*)(G + d);
                const float4 go4 = *(const float4*)(G + 256 + d);
                const float4 gu4 = *(const float4*)(G + 512 + d);
                const float4 f14 = *(const float4*)(G + 768 + d);
                const float4 f24 = *(const float4*)(G + 1024 + d);
                const float4 bi4 = *(const float4*)(Uib + d);
                const float4 bo4 = *(const float4*)(Uob + d);
                const float4 bu4 = *(const float4*)(Uub + d);
                const float4 bf4 = *(const float4*)(Ufb + d);
                const float4 c14 = *(const float4*)(g_stackc + base + (long)lix * DD + d);
                const float4 c24 = *(const float4*)(g_stackc + base + (long)rix * DD + d);
                float4 cn4, hn4;
#define CELL(M) { \
                const float ig = sigm(gi4.M + bi4.M); \
                const float og = sigm(go4.M + bo4.M); \
                const float ug = tanhf(gu4.M + bu4.M); \
                const float f1 = sigm(f14.M + bf4.M); \
                const float f2 = sigm(f24.M + bf4.M); \
                cn4.M = ig * ug + f1 * c14.M + f2 * c24.M; \
                hn4.M = og * tanhf(cn4.M); }
                CELL(x) CELL(y) CELL(z) CELL(w)
#undef CELL
                *(float4*)(g_stackc + base + (long)lix * DD + d) = cn4;
                *(float4*)(g_stackh + base + (long)lix * DD + d) = hn4;
            } else if (op == 0) {
                const long bi = ((long)b * SLEN + t) * DD + d;
                *(float4*)(g_stackh + base + (long)p * DD + d) = *(const float4*)(g_buffh + bi);
                *(float4*)(g_stackc + base + (long)p * DD + d) = *(const float4*)(g_buffc + bi);
            }
        }
        __syncthreads();
        if (tid < 64) {
            const int o = sm->sh_op[tid];
            sm->sh_p[tid] += (o == 0) ? 1 : ((o == 1) ? -1 : 0);
        }
        btile_bar(bt, mygen);
    }

    if (ct == 0) {
        for (int q = tid; q < 64 * 256; q += 256) {
            const int bl = q >> 8, d = q & 255;
            const int b = b0 + bl;
            const int ix = max(sm->sh_p[bl] - 1, 0);
            g_r[b * DD + d] = g_stackh[(long)b * STK * DD + (long)ix * DD + d];
        }
    }
}

// ---------------------------------------------------------------------------
// MEGA kernel roles (block ID ranges):
//   [0,160)       scan         (gated on g_combcnt == 252)
//   [160,944)     v  split     -> g_v2done[m]
//   [944,1196)    q  split     -> g_q2done[m]
//   [1196,4220)   leaf GEMM    (waits g_q2done)  -> g_leafdone[m] (12/tile)
//   [4220,4472)   leaf combine (waits g_leafdone) -> g_combcnt
//   [4472,7608)   vv GEMM      (waits g_v2done)  -> g_vvdone[m] (4/tile)
//   [7608,10744)  wvi GEMM     (waits g_vvdone == 4)
// All consumer waits except the scan's are on lower block IDs; the scan's
// producers fit in the free resident slots (>=296 total, scan holds 160).
// ---------------------------------------------------------------------------
__global__ __launch_bounds__(256, 2) void mega_k(
    const int* __restrict__ ops,
    const float* __restrict__ Ui, const float* __restrict__ Uo,
    const float* __restrict__ Uu, const float* __restrict__ Uf,
    const float* __restrict__ Uib, const float* __restrict__ Uob,
    const float* __restrict__ Uub, const float* __restrict__ Ufb,
    const float* __restrict__ v, const int* __restrict__ questions,
    const float* __restrict__ wembed, const float* __restrict__ Wb)
{
    __shared__ __align__(16) char raw[sizeof(MmaSmem)];
    const int bid = blockIdx.x;
    const int tid = threadIdx.x;

    if (bid < 160) {
        if (tid == 0)
            while (atomicAdd(&g_combcnt, 0u) < 252u) __nanosleep(500);
        __syncthreads();
        __threadfence();
        scan_core((ScanSmem*)raw, bid, ops, Ui, Uo, Uu, Uf, Uib, Uob, Uub, Ufb);
    } else if (bid < 944) {
        // v split: 128 rows x 512 cols -> bf16 hi|lo
        const int m = bid - 160;
        const long r0 = (long)m * 128;
        for (int e = tid * 4; e < 128 * 512; e += 1024) {
            const int rr = e >> 9, col = e & 511;
            const long row = r0 + rr;
            const float4 x = *(const float4*)(v + row * 512 + col);
            __nv_bfloat16* o = g_v2 + row * 1024;
            const __nv_bfloat16 h0 = __float2bfloat16(x.x), h1 = __float2bfloat16(x.y);
            const __nv_bfloat16 h2 = __float2bfloat16(x.z), h3 = __float2bfloat16(x.w);
            *(__nv_bfloat162*)(o + col)       = __nv_bfloat162(h0, h1);
            *(__nv_bfloat162*)(o + col + 2)   = __nv_bfloat162(h2, h3);
            *(__nv_bfloat162*)(o + 512 + col) = __nv_bfloat162(
                __float2bfloat16(x.x - __bfloat162float(h0)),
                __float2bfloat16(x.y - __bfloat162float(h1)));
            *(__nv_bfloat162*)(o + 512 + col + 2) = __nv_bfloat162(
                __float2bfloat16(x.z - __bfloat162float(h2)),
                __float2bfloat16(x.w - __bfloat162float(h3)));
        }
        __threadfence();
        __syncthreads();
        if (tid == 0) atomicExch(&g_v2done[m], 1u);
    } else if (bid < 1196) {
        // q split: gather wembed rows, 128 rows x 256 cols -> bf16 hi|lo
        const int m = bid - 944;
        for (int e = tid * 4; e < 128 * 256; e += 1024) {
            const int rr = e >> 8, col = e & 255;
            const long row = (long)m * 128 + rr;
            const long src = questions[row];
            const float4 x = *(const float4*)(wembed + src * 256 + col);
            __nv_bfloat16* o = g_q2 + row * 512;
            const __nv_bfloat16 h0 = __float2bfloat16(x.x), h1 = __float2bfloat16(x.y);
            const __nv_bfloat16 h2 = __float2bfloat16(x.z), h3 = __float2bfloat16(x.w);
            *(__nv_bfloat162*)(o + col)       = __nv_bfloat162(h0, h1);
            *(__nv_bfloat162*)(o + col + 2)   = __nv_bfloat162(h2, h3);
            *(__nv_bfloat162*)(o + 256 + col) = __nv_bfloat162(
                __float2bfloat16(x.x - __bfloat162float(h0)),
                __float2bfloat16(x.y - __bfloat162float(h1)));
            *(__nv_bfloat162*)(o + 256 + col + 2) = __nv_bfloat162(
                __float2bfloat16(x.z - __bfloat162float(h2)),
                __float2bfloat16(x.w - __bfloat162float(h3)));
        }
        __threadfence();
        __syncthreads();
        if (tid == 0) atomicExch(&g_q2done[m], 1u);
    } else if (bid < 4220) {
        // leaf gates GEMM
        const int idx = bid - 1196;
        const int m = idx / 12, n = idx % 12;
        if (tid == 0)
            while (atomicAdd(&g_q2done[m], 0u) == 0u) __nanosleep(200);
        __syncthreads();
        __threadfence();
        mma_core((MmaSmem*)raw, g_q2, g_w3iuo, g_biuo, g_gl, nullptr, DD, 768, 0, 3,
                 (long)m * 128, n * 64);
        __threadfence();
        __syncthreads();
        if (tid == 0) atomicAdd(&g_leafdone[m], 1u);
    } else if (bid < 4472) {
        // leaf combine
        const int m = bid - 4220;
        if (tid == 0)
            while (atomicAdd(&g_leafdone[m], 0u) < 12u) __nanosleep(200);
        __syncthreads();
        __threadfence();
        for (int e = tid; e < 128 * 256; e += 256) {
            const long row = (long)m * 128 + (e >> 8);
            const int d = e & 255;
            const float gi = g_gl[row * 768 + d];
            const float gu = g_gl[row * 768 + 256 + d];
            const float go = g_gl[row * 768 + 512 + d];
            const float bc = gi * gu;
            g_buffc[row * 256 + d] = bc;
            g_buffh[row * 256 + d] = go * tanhf(bc);
        }
        __threadfence();
        __syncthreads();
        if (tid == 0) atomicAdd(&g_combcnt, 1u);
    } else if (bid < 7608) {
        // vv GEMM
        const int idx = bid - 4472;
        const int m = idx >> 2;
        if (tid == 0)
            while (atomicAdd(&g_v2done[m], 0u) == 0u) __nanosleep(200);
        __syncthreads();
        __threadfence();
        mma_core((MmaSmem*)raw, g_v2, g_w3vv, Wb, g_vv, g_vv2, VDIM, DD, 0, 1,
                 (long)m * 128, (idx & 3) * 64);
        __threadfence();
        __syncthreads();
        if (tid == 0) atomicAdd(&g_vvdone[m], 1u);
    } else {
        // wvi GEMM
        const int idx = bid - 7608;
        const int m = idx >> 2;
        if (tid == 0)
            while (atomicAdd(&g_vvdone[m], 0u) < 4u) __nanosleep(200);
        __syncthreads();
        __threadfence();
        mma_core((MmaSmem*)raw, g_vv2, g_w3wv, nullptr, g_wvi, nullptr, DD, DD, 0, 0,
                 (long)m * 128, (idx & 3) * 64);
    }
}

// ---------------- weight splits, all in one kernel -----------------------------
__global__ void wsplit_all_k(const float* __restrict__ W_w,
                             const float* __restrict__ WV_w,
                             const float* __restrict__ Wi_w,
                             const float* __restrict__ Wu_w,
                             const float* __restrict__ Wo_w)
{
    const int b = blockIdx.x;
    const float* src;
    __nv_bfloat16* o;
    int K;
    if (b < 256)      { src = W_w  + (long)b * 512;         o = g_w3vv  + (long)b * 1536;        K = 512; }
    else if (b < 512) { src = WV_w + (long)(b - 256) * 256; o = g_w3wv  + (long)(b - 256) * 768; K = 256; }
    else {
        const int r = b - 512;
        const float* Ws = (r < 256) ? Wi_w : (r < 512) ? Wu_w : Wo_w;
        src = Ws + (long)(r & 255) * 256;
        o = g_w3iuo + (long)r * 768;
        K = 256;
    }
    for (int c = threadIdx.x; c < K; c += blockDim.x) {
        const float x = src[c];
        const __nv_bfloat16 h = __float2bfloat16(x);
        o[c] = h;
        o[K + c] = h;
        o[2 * K + c] = __float2bfloat16(x - __bfloat162float(h));
    }
}

// ---------------- prep: biases + flag reset -------------------------------------
__global__ void prep_k(const float* __restrict__ bi, const float* __restrict__ bu,
                       const float* __restrict__ bo)
{
    const int i = blockIdx.x * blockDim.x + threadIdx.x;
    if (i < 256)      g_biuo[i] = bi[i];
    else if (i < 512) g_biuo[i] = bu[i - 256];
    else if (i < 768) g_biuo[i] = bo[i - 512];
    if (i < 784) { g_v2done[i] = 0u; g_vvdone[i] = 0u; }
    if (i < 252) { g_q2done[i] = 0u; g_leafdone[i] = 0u; }
    if (i == 0)  g_combcnt = 0u;
}

// ---------------- fp32 packed GEMM (small matmuls) -----------------------------
__global__ __launch_bounds__(256) void gemm_k(
    const float* __restrict__ A, const int* __restrict__ rowidx,
    const float* __restrict__ W, const float* __restrict__ bias,
    float* __restrict__ C, int N, int K, int ldc, int coloff, int act)
{
    __shared__ float As[16][132];
    __shared__ float Ws[16][68];
    const int tid = threadIdx.x;
    const int tx = tid & 15, ty = tid >> 4;
    const int lr = tid >> 2, lc = tid & 3;
    const long bm = (long)blockIdx.x * 128;
    const int  bn = blockIdx.y * 64;

    long ar0 = bm + lr, ar1 = bm + lr + 64;
    if (rowidx) { ar0 = rowidx[ar0]; ar1 = rowidx[ar1]; }
    const float* Ap0 = A + ar0 * (long)K;
    const float* Ap1 = A + ar1 * (long)K;
    const int wr = bn + lr;
    const bool wok = (wr < N);
    const float* Wp = W + (long)wr * K;

    unsigned long long acc[4][4];
#pragma unroll
    for (int p = 0; p < 4; p++)
#pragma unroll
        for (int c = 0; c < 4; c++) acc[p][c] = 0ULL;

    for (int k0 = 0; k0 < K; k0 += 16) {
        float4 a0 = *(const float4*)(Ap0 + k0 + lc * 4);
        float4 a1 = *(const float4*)(Ap1 + k0 + lc * 4);
        float4 w0 = wok ? *(const float4*)(Wp + k0 + lc * 4)
                        : make_float4(0.f, 0.f, 0.f, 0.f);
        __syncthreads();
        As[lc*4+0][lr] = a0.x; As[lc*4+1][lr] = a0.y;
        As[lc*4+2][lr] = a0.z; As[lc*4+3][lr] = a0.w;
        As[lc*4+0][lr+64] = a1.x; As[lc*4+1][lr+64] = a1.y;
        As[lc*4+2][lr+64] = a1.z; As[lc*4+3][lr+64] = a1.w;
        Ws[lc*4+0][lr] = w0.x; Ws[lc*4+1][lr] = w0.y;
        Ws[lc*4+2][lr] = w0.z; Ws[lc*4+3][lr] = w0.w;
        __syncthreads();
#pragma unroll
        for (int k = 0; k < 16; k++) {
            const float4 aA = *(const float4*)&As[k][ty*8];
            const float4 aB = *(const float4*)&As[k][ty*8+4];
            const float4 bb = *(const float4*)&Ws[k][tx*4];
            unsigned long long ap[4] = { pk2(aA.x,aA.y), pk2(aA.z,aA.w),
                                         pk2(aB.x,aB.y), pk2(aB.z,aB.w) };
            unsigned long long bd[4] = { pk2(bb.x,bb.x), pk2(bb.y,bb.y),
                                         pk2(bb.z,bb.z), pk2(bb.w,bb.w) };
#pragma unroll
            for (int p = 0; p < 4; p++)
#pragma unroll
                for (int c = 0; c < 4; c++)
                    acc[p][c] = ff2(ap[p], bd[c], acc[p][c]);
        }
    }

#pragma unroll
    for (int p = 0; p < 4; p++) {
        const long r0 = bm + ty*8 + p*2;
#pragma unroll
        for (int c = 0; c < 4; c++) {
            const int col = bn + tx*4 + c;
            if (col < N) {
                float lo, hi; upk2(acc[p][c], lo, hi);
                const float bv = bias ? bias[col] : 0.0f;
                lo += bv; hi += bv;
                if (act == 1)      { lo = tanhf(lo); hi = tanhf(hi); }
                else if (act == 2) { lo = sigm(lo);  hi = sigm(hi);  }
                C[r0 * (long)ldc + coloff + col] = lo;
                C[(r0+1) * (long)ldc + coloff + col] = hi;
            }
        }
    }
}

__global__ void attention_k(const float* __restrict__ WPw,
                            const float* __restrict__ WPb)
{
    const int b = blockIdx.x, tid = threadIdx.x;
    const int warp = tid >> 5, lane = tid & 31;
    __shared__ float s_wq[256], s_wp[256], s_sc[RR], red[16];

    s_wq[tid] = g_wq[b * DD + tid];
    s_wp[tid] = WPw[tid];
    __syncthreads();

    const float wpb = WPb[0];
    for (int r = warp; r < RR; r += 8) {
        const float* vrow = g_wvi + ((long)b * RR + r) * DD;
        float acc = 0.f;
        for (int d = lane; d < DD; d += 32)
            acc += tanhf(s_wq[d] + vrow[d]) * s_wp[d];
#pragma unroll
        for (int o = 16; o; o >>= 1) acc += __shfl_xor_sync(~0u, acc, o);
        if (lane == 0) s_sc[r] = acc + wpb;
    }
    __syncthreads();

    float v = (tid < RR) ? s_sc[tid] : -1e30f;
    float m = v;
#pragma unroll
    for (int o = 16; o; o >>= 1) m = fmaxf(m, __shfl_xor_sync(~0u, m, o));
    if (lane == 0) red[warp] = m;
    __syncthreads();
    if (tid == 0) {
        float mm = red[0];
        for (int q = 1; q < 8; q++) mm = fmaxf(mm, red[q]);
        red[0] = mm;
    }
    __syncthreads();
    const float mm = red[0];
    float e = (tid < RR) ? expf(v - mm) : 0.f;
    float s = e;
#pragma unroll
    for (int o = 16; o; o >>= 1) s += __shfl_xor_sync(~0u, s, o);
    if (lane == 0) red[8 + warp] = s;
    __syncthreads();
    if (tid == 0) {
        float ss = 0.f;
        for (int q = 0; q < 8; q++) ss += red[8 + q];
        red[8] = ss;
    }
    __syncthreads();
    const float inv = 1.0f / red[8];
    if (tid < RR) s_sc[tid] = e * inv;
    __syncthreads();

    float acc = g_r[b * DD + tid];
    const float* vb = g_vv + (long)b * RR * DD;
    for (int r = 0; r < RR; r++)
        acc += s_sc[r] * vb[r * DD + tid];
    g_att[b * DD + tid] = acc;
}

// ---------------------------------------------------------------------------
template <typename T>
static void* symaddr_raw(T& sym) {
    void* p = nullptr;
    cudaGetSymbolAddress(&p, sym);
    return p;
}

extern "C" void kernel_launch(void* const* d_in, const int* in_sizes, int n_in,
                              void* d_out, int out_size)
{
    const float* v         = (const float*)d_in[0];
    const int*   questions = (const int*)d_in[1];
    const int*   ops       = (const int*)d_in[2];
    int i = (n_in >= 30) ? 4 : 3;
    const float* wembed = (const float*)d_in[i++];
    const float* W_w  = (const float*)d_in[i++]; const float* W_b  = (const float*)d_in[i++];
    const float* Wi_w = (const float*)d_in[i++]; const float* Wi_b = (const float*)d_in[i++];
    const float* Wu_w = (const float*)d_in[i++]; const float* Wu_b = (const float*)d_in[i++];
    const float* Wo_w = (const float*)d_in[i++]; const float* Wo_b = (const float*)d_in[i++];
    const float* Ui_w = (const float*)d_in[i++]; const float* Ui_b = (const float*)d_in[i++];
    const float* Uf_w = (const float*)d_in[i++]; const float* Uf_b = (const float*)d_in[i++];
    const float* Uo_w = (const float*)d_in[i++]; const float* Uo_b = (const float*)d_in[i++];
    const float* Uu_w = (const float*)d_in[i++]; const float* Uu_b = (const float*)d_in[i++];
    const float* WQ_w = (const float*)d_in[i++]; const float* WQ_b = (const float*)d_in[i++];
    const float* WV_w = (const float*)d_in[i++];
    const float* WP_w = (const float*)d_in[i++]; const float* WP_b = (const float*)d_in[i++];
    const float* FC1_w = (const float*)d_in[i++]; const float* FC1_b = (const float*)d_in[i++];
    const float* FC2_w = (const float*)d_in[i++]; const float* FC2_b = (const float*)d_in[i++];
    float* out = (float*)d_out;

    float* p_r   = (float*)symaddr_raw(g_r);
    float* p_wq  = (float*)symaddr_raw(g_wq);
    float* p_att = (float*)symaddr_raw(g_att);
    float* p_hid = (float*)symaddr_raw(g_hid);

    // 1-2: weight conversions + flag/bias prep
    wsplit_all_k<<<1280, 128>>>(W_w, WV_w, Wi_w, Wu_w, Wo_w);
    prep_k<<<4, 256>>>(Wi_b, Wu_b, Wo_b);

    // 3: MEGA — input splits, leaf gates+combine, scan, vv, wvi: ONE launch
    mega_k<<<10744, 256>>>(ops, Ui_w, Uo_w, Uu_w, Uf_w,
                           Ui_b, Uo_b, Uu_b, Uf_b,
                           v, questions, wembed, W_b);

    // 4-7: tail
    gemm_k<<<dim3(4, 4), 256>>>(p_r, nullptr, WQ_w, WQ_b, p_wq, DD, DD, DD, 0, 0);
    attention_k<<<BSZ, 256>>>(WP_w, WP_b);
    gemm_k<<<dim3(4, 4), 256>>>(p_att, nullptr, FC1_w, FC1_b, p_hid, DD, DD, DD, 0, 1);
    gemm_k<<<dim3(4, 47), 256>>>(p_hid, nullptr, FC2_w, FC2_b, out, NOUTD, DD, NOUTD, 0, 0);

    (void)in_sizes; (void)out_size;
}

// round 17
// speedup vs baseline: 1.1896x; 1.1896x over previous
#include <cuda_runtime.h>
#include <cuda_bf16.h>
#include <math.h>
#include <stdint.h>

#define BSZ   512
#define SLEN  63
#define DD    256
#define VDIM  512
#define RR    196
#define NOUTD 3000
#define STK   (SLEN + 2)

// ---------------- scratch (static device arrays; no allocation) -------------
__device__ float g_vv   [(size_t)BSZ * RR * DD];
__device__ float g_wvi  [(size_t)BSZ * RR * DD];
__device__ float g_gl   [(size_t)BSZ * SLEN * 768];
__device__ float g_buffh[(size_t)BSZ * SLEN * DD];
__device__ float g_buffc[(size_t)BSZ * SLEN * DD];
__device__ float g_stackh[(size_t)BSZ * STK * DD];
__device__ float g_stackc[(size_t)BSZ * STK * DD];
__device__ float g_gates[(size_t)BSZ * 1280];
__device__ float g_r    [BSZ * DD];
__device__ float g_att  [BSZ * DD];
__device__ float g_hid  [BSZ * DD];
__device__ float g_biuo [768];
__device__ unsigned g_bc[8];
__device__ unsigned g_bg[8];
__device__ unsigned g_v2done[784];
__device__ unsigned g_vvdone[784];

// bf16 split buffers
__device__ __nv_bfloat16 g_v2   [(size_t)BSZ * RR * (2 * VDIM)];
__device__ __nv_bfloat16 g_vv2  [(size_t)BSZ * RR * (2 * DD)];
__device__ __nv_bfloat16 g_q2   [(size_t)BSZ * SLEN * (2 * DD)];
__device__ __nv_bfloat16 g_w3vv [256 * 3 * VDIM];
__device__ __nv_bfloat16 g_w3wv [256 * 3 * DD];
__device__ __nv_bfloat16 g_w3iuo[768 * 3 * DD];

// ---------------- packed f32x2 helpers ---------------------------------------
__device__ __forceinline__ unsigned long long pk2(float lo, float hi) {
    unsigned long long r;
    asm("mov.b64 %0, {%1, %2};" : "=l"(r) : "f"(lo), "f"(hi));
    return r;
}
__device__ __forceinline__ void upk2(unsigned long long v, float& lo, float& hi) {
    asm("mov.b64 {%0, %1}, %2;" : "=f"(lo), "=f"(hi) : "l"(v));
}
__device__ __forceinline__ unsigned long long ff2(unsigned long long a,
                                                  unsigned long long b,
                                                  unsigned long long c) {
    unsigned long long d;
    asm("fma.rn.f32x2 %0, %1, %2, %3;" : "=l"(d) : "l"(a), "l"(b), "l"(c));
    return d;
}
__device__ __forceinline__ float sigm(float x) { return 1.0f / (1.0f + expf(-x)); }

__device__ __forceinline__ uint32_t smem_u32(const void* p) {
    uint32_t a;
    asm("{ .reg .u64 t; cvta.to.shared.u64 t, %1; cvt.u32.u64 %0, t; }"
        : "=r"(a) : "l"(p));
    return a;
}
__device__ __forceinline__ void ldmx4(uint32_t& r0, uint32_t& r1,
                                      uint32_t& r2, uint32_t& r3, uint32_t addr) {
    asm volatile("ldmatrix.sync.aligned.m8n8.x4.shared.b16 {%0,%1,%2,%3}, [%4];"
                 : "=r"(r0), "=r"(r1), "=r"(r2), "=r"(r3) : "r"(addr));
}
__device__ __forceinline__ void mma16816(float& d0, float& d1, float& d2, float& d3,
                                         uint32_t a0, uint32_t a1, uint32_t a2, uint32_t a3,
                                         uint32_t b0, uint32_t b1) {
    asm volatile("mma.sync.aligned.m16n8k16.row.col.f32.bf16.bf16.f32 "
                 "{%0,%1,%2,%3}, {%4,%5,%6,%7}, {%8,%9}, {%0,%1,%2,%3};"
                 : "+f"(d0), "+f"(d1), "+f"(d2), "+f"(d3)
                 : "r"(a0), "r"(a1), "r"(a2), "r"(a3), "r"(b0), "r"(b1));
}

__device__ __forceinline__ float apply_act(int act, int col, float x) {
    int e = act;
    if (act == 3) e = ((col >> 8) == 1) ? 1 : 2;
    if (e == 1)      return tanhf(x);
    else if (e == 2) return sigm(x);
    return x;
}

// ---------------- shared-memory layouts ---------------------------------------
#define APAD 72
struct MmaSmem {
    __nv_bfloat16 As[128 * APAD];
    __nv_bfloat16 Bs[64 * APAD];
};
struct ScanSmem {
    float As[16][68];
    float Ws[16][68];
    int   sh_op[64];
    int   sh_p[64];
    int   sh_any;
};

// ---------------------------------------------------------------------------
// Tensor-core (HMMA) split-bf16 GEMM core, tile 128(M) x 64(N). Proven form.
// ---------------------------------------------------------------------------
__device__ void mma_core(MmaSmem* sm,
                         const __nv_bfloat16* __restrict__ A2,
                         const __nv_bfloat16* __restrict__ W3,
                         const float* __restrict__ bias,
                         float* __restrict__ Cf,
                         __nv_bfloat16* __restrict__ Chl,
                         int K, int ldc, int coloff, int act,
                         long bm, int bn)
{
    __nv_bfloat16* As = sm->As;
    __nv_bfloat16* Bs = sm->Bs;

    const int tid = threadIdx.x;
    const int wid = tid >> 5, lane = tid & 31;
    const int warp_m = wid & 3, warp_n = wid >> 2;

    const int nc = K / 64;
    const int vchunks = 3 * nc;
    const long lda = 2L * K;
    const long ldw = 3L * K;

    const int a_row = (lane & 7) + ((lane & 8) ? 8 : 0);
    const int a_col = (lane & 16) ? 8 : 0;
    const int b_row = (lane & 7) + ((lane & 16) ? 8 : 0);
    const int b_col = (lane & 8) ? 8 : 0;
    const uint32_t as_base = smem_u32(As);
    const uint32_t bs_base = smem_u32(Bs);

    float d[2][4][4];
#pragma unroll
    for (int mt = 0; mt < 2; mt++)
#pragma unroll
        for (int nt = 0; nt < 4; nt++)
#pragma unroll
            for (int e = 0; e < 4; e++) d[mt][nt][e] = 0.0f;

    uint4 pa[4], pb[2];
    {
#pragma unroll
        for (int q = 0; q < 4; q++) {
            const int u = tid + 256 * q;
            pa[q] = *(const uint4*)(A2 + (bm + (u >> 3)) * lda + (u & 7) * 8);
        }
#pragma unroll
        for (int q = 0; q < 2; q++) {
            const int u = tid + 256 * q;
            pb[q] = *(const uint4*)(W3 + (long)(bn + (u >> 3)) * ldw + (u & 7) * 8);
        }
    }

    for (int c = 0; c < vchunks; c++) {
#pragma unroll
        for (int q = 0; q < 4; q++) {
            const int u = tid + 256 * q;
            *(uint4*)(As + (u >> 3) * APAD + (u & 7) * 8) = pa[q];
        }
#pragma unroll
        for (int q = 0; q < 2; q++) {
            const int u = tid + 256 * q;
            *(uint4*)(Bs + (u >> 3) * APAD + (u & 7) * 8) = pb[q];
        }
        __syncthreads();

        if (c + 1 < vchunks) {
            const int cn = c + 1;
            const long ca = (long)((cn < 2 * nc) ? cn : (cn - 2 * nc)) * 64;
            const long cw = (long)cn * 64;
#pragma unroll
            for (int q = 0; q < 4; q++) {
                const int u = tid + 256 * q;
                pa[q] = *(const uint4*)(A2 + (bm + (u >> 3)) * lda + ca + (u & 7) * 8);
            }
#pragma unroll
            for (int q = 0; q < 2; q++) {
                const int u = tid + 256 * q;
                pb[q] = *(const uint4*)(W3 + (long)(bn + (u >> 3)) * ldw + cw + (u & 7) * 8);
            }
        }

#pragma unroll
        for (int kk = 0; kk < 4; kk++) {
            uint32_t b0, b1, b2, b3, b4, b5, b6, b7;
            {
                const int r = warp_n * 32 + b_row;
                const int cc = kk * 16 + b_col;
                ldmx4(b0, b1, b2, b3, bs_base + (r * APAD + cc) * 2);
                ldmx4(b4, b5, b6, b7, bs_base + ((r + 16) * APAD + cc) * 2);
            }
#pragma unroll
            for (int mt = 0; mt < 2; mt++) {
                uint32_t a0, a1, a2, a3;
                const int r = warp_m * 32 + mt * 16 + a_row;
                const int cc = kk * 16 + a_col;
                ldmx4(a0, a1, a2, a3, as_base + (r * APAD + cc) * 2);
                mma16816(d[mt][0][0], d[mt][0][1], d[mt][0][2], d[mt][0][3],
                         a0, a1, a2, a3, b0, b1);
                mma16816(d[mt][1][0], d[mt][1][1], d[mt][1][2], d[mt][1][3],
                         a0, a1, a2, a3, b2, b3);
                mma16816(d[mt][2][0], d[mt][2][1], d[mt][2][2], d[mt][2][3],
                         a0, a1, a2, a3, b4, b5);
                mma16816(d[mt][3][0], d[mt][3][1], d[mt][3][2], d[mt][3][3],
                         a0, a1, a2, a3, b6, b7);
            }
        }
        __syncthreads();
    }

    const int qrow = lane >> 2;
    const int qcol = (lane & 3) * 2;
#pragma unroll
    for (int mt = 0; mt < 2; mt++) {
#pragma unroll
        for (int nt = 0; nt < 4; nt++) {
            const int colg = bn + warp_n * 32 + nt * 8 + qcol;
            const float bv0 = bias ? bias[colg]     : 0.0f;
            const float bv1 = bias ? bias[colg + 1] : 0.0f;
#pragma unroll
            for (int h = 0; h < 2; h++) {
                const long grow = bm + warp_m * 32 + mt * 16 + qrow + h * 8;
                float x0 = apply_act(act, coloff + colg,     d[mt][nt][2*h+0] + bv0);
                float x1 = apply_act(act, coloff + colg + 1, d[mt][nt][2*h+1] + bv1);
                *(float2*)(Cf + grow * ldc + coloff + colg) = make_float2(x0, x1);
                if (Chl) {
                    const __nv_bfloat16 h0 = __float2bfloat16(x0);
                    const __nv_bfloat16 h1 = __float2bfloat16(x1);
                    *(__nv_bfloat162*)(Chl + grow * 512 + colg) = __nv_bfloat162(h0, h1);
                    *(__nv_bfloat162*)(Chl + grow * 512 + 256 + colg) = __nv_bfloat162(
                        __float2bfloat16(x0 - __bfloat162float(h0)),
                        __float2bfloat16(x1 - __bfloat162float(h1)));
                }
            }
        }
    }
}

__global__ __launch_bounds__(256) void mma_gemm(
    const __nv_bfloat16* __restrict__ A2,
    const __nv_bfloat16* __restrict__ W3,
    const float* __restrict__ bias,
    float* __restrict__ Cf,
    __nv_bfloat16* __restrict__ Chl,
    int K, int ldc, int coloff, int act)
{
    __shared__ MmaSmem sm;
    mma_core(&sm, A2, W3, bias, Cf, Chl, K, ldc, coloff, act,
             (long)blockIdx.x * 128, blockIdx.y * 64);
}

// ---------------------------------------------------------------------------
// Persistent shift-reduce scan core (proven), 8 btiles x 20 ctiles.
// ---------------------------------------------------------------------------
__device__ __forceinline__ void btile_bar(int bt, unsigned& mygen)
{
    __threadfence();
    __syncthreads();
    if (threadIdx.x == 0) {
        if (atomicAdd(&g_bc[bt], 1u) == 19u) {
            atomicExch(&g_bc[bt], 0u);
            __threadfence();
            atomicAdd(&g_bg[bt], 1u);
        } else {
            while (atomicAdd(&g_bg[bt], 0u) <= mygen) { }
        }
        mygen++;
    }
    __syncthreads();
}

__device__ void scan_core(ScanSmem* sm, int scanblk,
                          const int* __restrict__ ops,
                          const float* __restrict__ Ui, const float* __restrict__ Uo,
                          const float* __restrict__ Uu, const float* __restrict__ Uf,
                          const float* __restrict__ Uib, const float* __restrict__ Uob,
                          const float* __restrict__ Uub, const float* __restrict__ Ufb)
{
    const int tid = threadIdx.x;
    const int bt = scanblk / 20;
    const int ct = scanblk % 20;
    const int b0 = bt * 64;
    const int seg = ct >> 2;
    const int colbase = (ct & 3) * 64;
    const float* W = (seg == 0) ? Ui : (seg == 1) ? Uo : (seg == 2) ? Uu : Uf;

    const int tx = tid & 15, ty = tid >> 4;
    const int lr = tid >> 2, lc = tid & 3;

    unsigned mygen = 0;
    if (tid == 0) mygen = atomicAdd(&g_bg[bt], 0u);
    if (tid < 64) sm->sh_p[tid] = 0;
    __syncthreads();

    for (int t = 0; t < SLEN; t++) {
        if (tid == 0) sm->sh_any = 0;
        __syncthreads();
        if (tid < 64) {
            const int o = ops[(b0 + tid) * SLEN + t];
            sm->sh_op[tid] = o;
            if (o == 1) sm->sh_any = 1;
        }
        __syncthreads();

        if (sm->sh_any) {
            const int pcur = sm->sh_p[lr];
            const float* Wp = W + (long)(colbase + lr) * DD;
            const float* SHb = g_stackh + (long)(b0 + lr) * STK * DD;
            const float* Sr = SHb + (long)max(pcur - 1, 0) * DD;
            const float* Sl = SHb + (long)max(pcur - 2, 0) * DD;

            unsigned long long acc[2][4];
#pragma unroll
            for (int p = 0; p < 2; p++)
#pragma unroll
                for (int c = 0; c < 4; c++) acc[p][c] = 0ULL;

            for (int k0 = 0; k0 < DD; k0 += 16) {
                float4 av;
                if (seg < 3) {
                    const float4 x = *(const float4*)(Sr + k0 + lc*4);
                    const float4 y = *(const float4*)(Sl + k0 + lc*4);
                    av = make_float4(x.x+y.x, x.y+y.y, x.z+y.z, x.w+y.w);
                } else if (seg == 3) {
                    av = *(const float4*)(Sl + k0 + lc*4);
                } else {
                    av = *(const float4*)(Sr + k0 + lc*4);
                }
                const float4 wv = *(const float4*)(Wp + k0 + lc*4);
                __syncthreads();
                sm->As[lc*4+0][lr] = av.x; sm->As[lc*4+1][lr] = av.y;
                sm->As[lc*4+2][lr] = av.z; sm->As[lc*4+3][lr] = av.w;
                sm->Ws[lc*4+0][lr] = wv.x; sm->Ws[lc*4+1][lr] = wv.y;
                sm->Ws[lc*4+2][lr] = wv.z; sm->Ws[lc*4+3][lr] = wv.w;
                __syncthreads();
#pragma unroll
                for (int k = 0; k < 16; k++) {
                    const float4 aa = *(const float4*)&sm->As[k][ty*4];
                    const float4 bb = *(const float4*)&sm->Ws[k][tx*4];
                    unsigned long long ap[2] = { pk2(aa.x,aa.y), pk2(aa.z,aa.w) };
                    unsigned long long bd[4] = { pk2(bb.x,bb.x), pk2(bb.y,bb.y),
                                                 pk2(bb.z,bb.z), pk2(bb.w,bb.w) };
#pragma unroll
                    for (int p = 0; p < 2; p++)
#pragma unroll
                        for (int c = 0; c < 4; c++)
                            acc[p][c] = ff2(ap[p], bd[c], acc[p][c]);
                }
            }
#pragma unroll
            for (int p = 0; p < 2; p++) {
                const long row = b0 + ty*4 + p*2;
#pragma unroll
                for (int c = 0; c < 4; c++) {
                    const int col = seg * 256 + colbase + tx*4 + c;
                    float lo, hi; upk2(acc[p][c], lo, hi);
                    g_gates[row * 1280 + col] = lo;
                    g_gates[(row+1) * 1280 + col] = hi;
                }
            }
            btile_bar(bt, mygen);
        }

        if (ct < 16) {
            const int bl = tid >> 2;
            const int d = ct * 16 + (tid & 3) * 4;
            const int op = sm->sh_op[bl];
            const int p = sm->sh_p[bl];
            const int b = b0 + bl;
            const long base = (long)b * STK * DD;
            if (op == 1) {
                const int rix = max(p - 1, 0);
                const int lix = max(p - 2, 0);
                const float* G = g_gates + (long)b * 1280;
                const float4 gi4 = *(const float4*)(G + d);
                const float4 go4 = *(const float4*)(G + 256 + d);
                const float4 gu4 = *(const float4*)(G + 512 + d);
                const float4 f14 = *(const float4*)(G + 768 + d);
                const float4 f24 = *(const float4*)(G + 1024 + d);
                const float4 bi4 = *(const float4*)(Uib + d);
                const float4 bo4 = *(const float4*)(Uob + d);
                const float4 bu4 = *(const float4*)(Uub + d);
                const float4 bf4 = *(const float4*)(Ufb + d);
                const float4 c14 = *(const float4*)(g_stackc + base + (long)lix * DD + d);
                const float4 c24 = *(const float4*)(g_stackc + base + (long)rix * DD + d);
                float4 cn4, hn4;
#define CELL(M) { \
                const float ig = sigm(gi4.M + bi4.M); \
                const float og = sigm(go4.M + bo4.M); \
                const float ug = tanhf(gu4.M + bu4.M); \
                const float f1 = sigm(f14.M + bf4.M); \
                const float f2 = sigm(f24.M + bf4.M); \
                cn4.M = ig * ug + f1 * c14.M + f2 * c24.M; \
                hn4.M = og * tanhf(cn4.M); }
                CELL(x) CELL(y) CELL(z) CELL(w)
#undef CELL
                *(float4*)(g_stackc + base + (long)lix * DD + d) = cn4;
                *(float4*)(g_stackh + base + (long)lix * DD + d) = hn4;
            } else if (op == 0) {
                const long bi = ((long)b * SLEN + t) * DD + d;
                *(float4*)(g_stackh + base + (long)p * DD + d) = *(const float4*)(g_buffh + bi);
                *(float4*)(g_stackc + base + (long)p * DD + d) = *(const float4*)(g_buffc + bi);
            }
        }
        __syncthreads();
        if (tid < 64) {
            const int o = sm->sh_op[tid];
            sm->sh_p[tid] += (o == 0) ? 1 : ((o == 1) ? -1 : 0);
        }
        btile_bar(bt, mygen);
    }

    if (ct == 0) {
        for (int q = tid; q < 64 * 256; q += 256) {
            const int bl = q >> 8, d = q & 255;
            const int b = b0 + bl;
            const int ix = max(sm->sh_p[bl] - 1, 0);
            g_r[b * DD + d] = g_stackh[(long)b * STK * DD + (long)ix * DD + d];
        }
    }
}

// ---------------------------------------------------------------------------
// MEGA kernel roles (block ID ranges):
//   [0,160)        scan (NO gate - starts immediately)
//   [160,944)      v split  -> g_v2done[m]
//   [944,4080)     vv GEMM  (waits g_v2done[m])  -> g_vvdone[m] (4/tile)
//   [4080,7216)    wvi GEMM (waits g_vvdone[m] == 4)
// Consumers wait only on lower block IDs -> no deadlock (R15-proven pattern).
// ---------------------------------------------------------------------------
__global__ __launch_bounds__(256, 2) void mega_k(
    const int* __restrict__ ops,
    const float* __restrict__ Ui, const float* __restrict__ Uo,
    const float* __restrict__ Uu, const float* __restrict__ Uf,
    const float* __restrict__ Uib, const float* __restrict__ Uob,
    const float* __restrict__ Uub, const float* __restrict__ Ufb,
    const float* __restrict__ v, const float* __restrict__ Wb)
{
    __shared__ __align__(16) char raw[sizeof(MmaSmem)];
    const int bid = blockIdx.x;
    const int tid = threadIdx.x;

    if (bid < 160) {
        scan_core((ScanSmem*)raw, bid, ops, Ui, Uo, Uu, Uf, Uib, Uob, Uub, Ufb);
    } else if (bid < 944) {
        // v split: 128 rows x 512 cols -> bf16 hi|lo
        const int m = bid - 160;
        const long r0 = (long)m * 128;
        for (int e = tid * 4; e < 128 * 512; e += 1024) {
            const int rr = e >> 9, col = e & 511;
            const long row = r0 + rr;
            const float4 x = *(const float4*)(v + row * 512 + col);
            __nv_bfloat16* o = g_v2 + row * 1024;
            const __nv_bfloat16 h0 = __float2bfloat16(x.x), h1 = __float2bfloat16(x.y);
            const __nv_bfloat16 h2 = __float2bfloat16(x.z), h3 = __float2bfloat16(x.w);
            *(__nv_bfloat162*)(o + col)       = __nv_bfloat162(h0, h1);
            *(__nv_bfloat162*)(o + col + 2)   = __nv_bfloat162(h2, h3);
            *(__nv_bfloat162*)(o + 512 + col) = __nv_bfloat162(
                __float2bfloat16(x.x - __bfloat162float(h0)),
                __float2bfloat16(x.y - __bfloat162float(h1)));
            *(__nv_bfloat162*)(o + 512 + col + 2) = __nv_bfloat162(
                __float2bfloat16(x.z - __bfloat162float(h2)),
                __float2bfloat16(x.w - __bfloat162float(h3)));
        }
        __threadfence();
        __syncthreads();
        if (tid == 0) atomicExch(&g_v2done[m], 1u);
    } else if (bid < 4080) {
        // vv GEMM
        const int idx = bid - 944;
        const int m = idx >> 2;
        if (tid == 0)
            while (atomicAdd(&g_v2done[m], 0u) == 0u) __nanosleep(200);
        __syncthreads();
        __threadfence();
        mma_core((MmaSmem*)raw, g_v2, g_w3vv, Wb, g_vv, g_vv2, VDIM, DD, 0, 1,
                 (long)m * 128, (idx & 3) * 64);
        __threadfence();
        __syncthreads();
        if (tid == 0) atomicAdd(&g_vvdone[m], 1u);
    } else {
        // wvi GEMM
        const int idx = bid - 4080;
        const int m = idx >> 2;
        if (tid == 0)
            while (atomicAdd(&g_vvdone[m], 0u) < 4u) __nanosleep(200);
        __syncthreads();
        __threadfence();
        mma_core((MmaSmem*)raw, g_vv2, g_w3wv, nullptr, g_wvi, nullptr, DD, DD, 0, 0,
                 (long)m * 128, (idx & 3) * 64);
    }
}

// ---------------- q split (gather wembed) --------------------------------------
__global__ void split2_k(const float* __restrict__ A, const int* __restrict__ gidx,
                         __nv_bfloat16* __restrict__ O, int K)
{
    const long r = blockIdx.x;
    const long src = gidx ? (long)gidx[r] : r;
    const float* a = A + src * K;
    __nv_bfloat16* o = O + r * (2L * K);
    const int c = threadIdx.x * 4;
    if (c < K) {
        const float4 x = *(const float4*)(a + c);
        const __nv_bfloat16 h0 = __float2bfloat16(x.x), h1 = __float2bfloat16(x.y);
        const __nv_bfloat16 h2 = __float2bfloat16(x.z), h3 = __float2bfloat16(x.w);
        *(__nv_bfloat162*)(o + c)     = __nv_bfloat162(h0, h1);
        *(__nv_bfloat162*)(o + c + 2) = __nv_bfloat162(h2, h3);
        *(__nv_bfloat162*)(o + K + c) = __nv_bfloat162(
            __float2bfloat16(x.x - __bfloat162float(h0)),
            __float2bfloat16(x.y - __bfloat162float(h1)));
        *(__nv_bfloat162*)(o + K + c + 2) = __nv_bfloat162(
            __float2bfloat16(x.z - __bfloat162float(h2)),
            __float2bfloat16(x.w - __bfloat162float(h3)));
    }
}

// ---------------- all weight splits in one kernel -------------------------------
__global__ void wsplit_all_k(const float* __restrict__ W_w,
                             const float* __restrict__ WV_w,
                             const float* __restrict__ Wi_w,
                             const float* __restrict__ Wu_w,
                             const float* __restrict__ Wo_w)
{
    const int b = blockIdx.x;
    const float* src;
    __nv_bfloat16* o;
    int K;
    if (b < 256)      { src = W_w  + (long)b * 512;         o = g_w3vv  + (long)b * 1536;        K = 512; }
    else if (b < 512) { src = WV_w + (long)(b - 256) * 256; o = g_w3wv  + (long)(b - 256) * 768; K = 256; }
    else {
        const int r = b - 512;
        const float* Ws = (r < 256) ? Wi_w : (r < 512) ? Wu_w : Wo_w;
        src = Ws + (long)(r & 255) * 256;
        o = g_w3iuo + (long)r * 768;
        K = 256;
    }
    for (int c = threadIdx.x; c < K; c += blockDim.x) {
        const float x = src[c];
        const __nv_bfloat16 h = __float2bfloat16(x);
        o[c] = h;
        o[K + c] = h;
        o[2 * K + c] = __float2bfloat16(x - __bfloat162float(h));
    }
}

// ---------------- prep: biases + flag reset -------------------------------------
__global__ void prep_k(const float* __restrict__ bi, const float* __restrict__ bu,
                       const float* __restrict__ bo)
{
    const int i = blockIdx.x * blockDim.x + threadIdx.x;
    if (i < 256)      g_biuo[i] = bi[i];
    else if (i < 512) g_biuo[i] = bu[i - 256];
    else if (i < 768) g_biuo[i] = bo[i - 512];
    if (i < 784) { g_v2done[i] = 0u; g_vvdone[i] = 0u; }
}

// ---------------- fp32 packed GEMM (small matmuls) -----------------------------
__global__ __launch_bounds__(256) void gemm_k(
    const float* __restrict__ A, const int* __restrict__ rowidx,
    const float* __restrict__ W, const float* __restrict__ bias,
    float* __restrict__ C, int N, int K, int ldc, int coloff, int act)
{
    __shared__ float As[16][132];
    __shared__ float Ws[16][68];
    const int tid = threadIdx.x;
    const int tx = tid & 15, ty = tid >> 4;
    const int lr = tid >> 2, lc = tid & 3;
    const long bm = (long)blockIdx.x * 128;
    const int  bn = blockIdx.y * 64;

    long ar0 = bm + lr, ar1 = bm + lr + 64;
    if (rowidx) { ar0 = rowidx[ar0]; ar1 = rowidx[ar1]; }
    const float* Ap0 = A + ar0 * (long)K;
    const float* Ap1 = A + ar1 * (long)K;
    const int wr = bn + lr;
    const bool wok = (wr < N);
    const float* Wp = W + (long)wr * K;

    unsigned long long acc[4][4];
#pragma unroll
    for (int p = 0; p < 4; p++)
#pragma unroll
        for (int c = 0; c < 4; c++) acc[p][c] = 0ULL;

    for (int k0 = 0; k0 < K; k0 += 16) {
        float4 a0 = *(const float4*)(Ap0 + k0 + lc * 4);
        float4 a1 = *(const float4*)(Ap1 + k0 + lc * 4);
        float4 w0 = wok ? *(const float4*)(Wp + k0 + lc * 4)
                        : make_float4(0.f, 0.f, 0.f, 0.f);
        __syncthreads();
        As[lc*4+0][lr] = a0.x; As[lc*4+1][lr] = a0.y;
        As[lc*4+2][lr] = a0.z; As[lc*4+3][lr] = a0.w;
        As[lc*4+0][lr+64] = a1.x; As[lc*4+1][lr+64] = a1.y;
        As[lc*4+2][lr+64] = a1.z; As[lc*4+3][lr+64] = a1.w;
        Ws[lc*4+0][lr] = w0.x; Ws[lc*4+1][lr] = w0.y;
        Ws[lc*4+2][lr] = w0.z; Ws[lc*4+3][lr] = w0.w;
        __syncthreads();
#pragma unroll
        for (int k = 0; k < 16; k++) {
            const float4 aA = *(const float4*)&As[k][ty*8];
            const float4 aB = *(const float4*)&As[k][ty*8+4];
            const float4 bb = *(const float4*)&Ws[k][tx*4];
            unsigned long long ap[4] = { pk2(aA.x,aA.y), pk2(aA.z,aA.w),
                                         pk2(aB.x,aB.y), pk2(aB.z,aB.w) };
            unsigned long long bd[4] = { pk2(bb.x,bb.x), pk2(bb.y,bb.y),
                                         pk2(bb.z,bb.z), pk2(bb.w,bb.w) };
#pragma unroll
            for (int p = 0; p < 4; p++)
#pragma unroll
                for (int c = 0; c < 4; c++)
                    acc[p][c] = ff2(ap[p], bd[c], acc[p][c]);
        }
    }

#pragma unroll
    for (int p = 0; p < 4; p++) {
        const long r0 = bm + ty*8 + p*2;
#pragma unroll
        for (int c = 0; c < 4; c++) {
            const int col = bn + tx*4 + c;
            if (col < N) {
                float lo, hi; upk2(acc[p][c], lo, hi);
                const float bv = bias ? bias[col] : 0.0f;
                lo += bv; hi += bv;
                if (act == 1)      { lo = tanhf(lo); hi = tanhf(hi); }
                else if (act == 2) { lo = sigm(lo);  hi = sigm(hi);  }
                C[r0 * (long)ldc + coloff + col] = lo;
                C[(r0+1) * (long)ldc + coloff + col] = hi;
            }
        }
    }
}

// ---------------- leaf combine --------------------------------------------------
__global__ void leaf_combine_k()
{
    const long i = (long)blockIdx.x * blockDim.x + threadIdx.x;
    const long row = i >> 8;
    const int  d = (int)(i & 255);
    const float gi = g_gl[row*768 + d];
    const float gu = g_gl[row*768 + 256 + d];
    const float go = g_gl[row*768 + 512 + d];
    const float bc = gi * gu;
    g_buffc[i] = bc;
    g_buffh[i] = go * tanhf(bc);
}

// ---------------- attention with fused wq = r @ WQ^T + b ------------------------
__global__ void attention_k(const float* __restrict__ WQw,
                            const float* __restrict__ WQb,
                            const float* __restrict__ WPw,
                            const float* __restrict__ WPb)
{
    const int b = blockIdx.x, tid = threadIdx.x;
    const int warp = tid >> 5, lane = tid & 31;
    __shared__ float s_r[256], s_wq[256], s_wp[256], s_sc[RR], red[16];

    s_r[tid] = g_r[b * DD + tid];
    s_wp[tid] = WPw[tid];
    __syncthreads();

    // wq[d] = dot(r, WQw[d,:]) + WQb[d]; warp w computes d in [w*32, w*32+32)
    for (int d = warp * 32; d < warp * 32 + 32; d++) {
        const float* wrow = WQw + (long)d * DD;
        float acc = 0.f;
        for (int k = lane; k < DD; k += 32) acc += s_r[k] * wrow[k];
#pragma unroll
        for (int o = 16; o; o >>= 1) acc += __shfl_xor_sync(~0u, acc, o);
        if (lane == 0) s_wq[d] = acc + WQb[d];
    }
    __syncthreads();

    const float wpb = WPb[0];
    for (int r = warp; r < RR; r += 8) {
        const float* vrow = g_wvi + ((long)b * RR + r) * DD;
        float acc = 0.f;
        for (int d = lane; d < DD; d += 32)
            acc += tanhf(s_wq[d] + vrow[d]) * s_wp[d];
#pragma unroll
        for (int o = 16; o; o >>= 1) acc += __shfl_xor_sync(~0u, acc, o);
        if (lane == 0) s_sc[r] = acc + wpb;
    }
    __syncthreads();

    float v = (tid < RR) ? s_sc[tid] : -1e30f;
    float m = v;
#pragma unroll
    for (int o = 16; o; o >>= 1) m = fmaxf(m, __shfl_xor_sync(~0u, m, o));
    if (lane == 0) red[warp] = m;
    __syncthreads();
    if (tid == 0) {
        float mm = red[0];
        for (int q = 1; q < 8; q++) mm = fmaxf(mm, red[q]);
        red[0] = mm;
    }
    __syncthreads();
    const float mm = red[0];
    float e = (tid < RR) ? expf(v - mm) : 0.f;
    float s = e;
#pragma unroll
    for (int o = 16; o; o >>= 1) s += __shfl_xor_sync(~0u, s, o);
    if (lane == 0) red[8 + warp] = s;
    __syncthreads();
    if (tid == 0) {
        float ss = 0.f;
        for (int q = 0; q < 8; q++) ss += red[8 + q];
        red[8] = ss;
    }
    __syncthreads();
    const float inv = 1.0f / red[8];
    if (tid < RR) s_sc[tid] = e * inv;
    __syncthreads();

    float acc = s_r[tid];
    const float* vb = g_vv + (long)b * RR * DD;
    for (int r = 0; r < RR; r++)
        acc += s_sc[r] * vb[r * DD + tid];
    g_att[b * DD + tid] = acc;
}

// ---------------------------------------------------------------------------
template <typename T>
static void* symaddr_raw(T& sym) {
    void* p = nullptr;
    cudaGetSymbolAddress(&p, sym);
    return p;
}

extern "C" void kernel_launch(void* const* d_in, const int* in_sizes, int n_in,
                              void* d_out, int out_size)
{
    const float* v         = (const float*)d_in[0];
    const int*   questions = (const int*)d_in[1];
    const int*   ops       = (const int*)d_in[2];
    int i = (n_in >= 30) ? 4 : 3;
    const float* wembed = (const float*)d_in[i++];
    const float* W_w  = (const float*)d_in[i++]; const float* W_b  = (const float*)d_in[i++];
    const float* Wi_w = (const float*)d_in[i++]; const float* Wi_b = (const float*)d_in[i++];
    const float* Wu_w = (const float*)d_in[i++]; const float* Wu_b = (const float*)d_in[i++];
    const float* Wo_w = (const float*)d_in[i++]; const float* Wo_b = (const float*)d_in[i++];
    const float* Ui_w = (const float*)d_in[i++]; const float* Ui_b = (const float*)d_in[i++];
    const float* Uf_w = (const float*)d_in[i++]; const float* Uf_b = (const float*)d_in[i++];
    const float* Uo_w = (const float*)d_in[i++]; const float* Uo_b = (const float*)d_in[i++];
    const float* Uu_w = (const float*)d_in[i++]; const float* Uu_b = (const float*)d_in[i++];
    const float* WQ_w = (const float*)d_in[i++]; const float* WQ_b = (const float*)d_in[i++];
    const float* WV_w = (const float*)d_in[i++];
    const float* WP_w = (const float*)d_in[i++]; const float* WP_b = (const float*)d_in[i++];
    const float* FC1_w = (const float*)d_in[i++]; const float* FC1_b = (const float*)d_in[i++];
    const float* FC2_w = (const float*)d_in[i++]; const float* FC2_b = (const float*)d_in[i++];
    float* out = (float*)d_out;

    float* p_gl  = (float*)symaddr_raw(g_gl);
    float* p_att = (float*)symaddr_raw(g_att);
    float* p_hid = (float*)symaddr_raw(g_hid);
    float* p_biuo = (float*)symaddr_raw(g_biuo);
    __nv_bfloat16* p_q2 = (__nv_bfloat16*)symaddr_raw(g_q2);
    __nv_bfloat16* p_w3iuo = (__nv_bfloat16*)symaddr_raw(g_w3iuo);

    // pre-mega (scan depends on leaf combine, so it stays outside)
    wsplit_all_k<<<1280, 128>>>(W_w, WV_w, Wi_w, Wu_w, Wo_w);
    prep_k<<<4, 256>>>(Wi_b, Wu_b, Wo_b);
    split2_k<<<BSZ * SLEN, 128>>>(wembed, questions, p_q2, DD);
    mma_gemm<<<dim3(252, 12), 256>>>(p_q2, p_w3iuo, p_biuo, p_gl, nullptr, DD, 768, 0, 3);
    leaf_combine_k<<<BSZ * SLEN, 256>>>();

    // MEGA: scan (immediate) + v split + vv + wvi, one launch
    mega_k<<<7216, 256>>>(ops, Ui_w, Uo_w, Uu_w, Uf_w,
                          Ui_b, Uo_b, Uu_b, Uf_b, v, W_b);

    // tail (wq fused into attention)
    attention_k<<<BSZ, 256>>>(WQ_w, WQ_b, WP_w, WP_b);
    gemm_k<<<dim3(4, 4), 256>>>(p_att, nullptr, FC1_w, FC1_b, p_hid, DD, DD, DD, 0, 1);
    gemm_k<<<dim3(4, 47), 256>>>(p_hid, nullptr, FC2_w, FC2_b, out, NOUTD, DD, NOUTD, 0, 0);

    (void)in_sizes; (void)out_size;
}